// round 11
// baseline (speedup 1.0000x reference)
#include <cuda_runtime.h>
#include <cuda.h>
#include <cuda_bf16.h>
#include <math.h>

// ---------------------------------------------------------------------------
// Problem constants
// ---------------------------------------------------------------------------
#define BATCH 16
#define LSEQ  2048
#define DIM   512
#define CDIST 21
#define CLIPD 10

// GEMM tiling
#define TILE 128                 // CTA tile: 128 x 128, 4 warps of 64x64
#define NTILE (LSEQ / TILE)      // 16
#define NPAIRS (NTILE * (NTILE + 1) / 2)   // 136
#define KCHUNK 32                // bf16 K elems per TMA stage (64 B rows)
#define NCHUNK (DIM / KCHUNK)    // 16
#define NSTAGES 3
#define ROWB 64
#define ARR_B (128 * ROWB)       // 8192 B
#define STAGE_B (4 * ARR_B)      // 32768 B (Ahi, Alo, Bhi, Blo)
#define PIPE_B (NSTAGES * STAGE_B)          // 98304
#define SMEM_BYTES (PIPE_B + 64 + 1024)
#define NTHREADS 128

// ---------------------------------------------------------------------------
// Device scratch
// ---------------------------------------------------------------------------
__device__ __align__(1024) __nv_bfloat16 g_khi[BATCH * LSEQ * DIM];
__device__ __align__(1024) __nv_bfloat16 g_klo[BATCH * LSEQ * DIM];
__device__ float g_kp[BATCH * LSEQ * CDIST];
__device__ int   g_mask_i32;

// ---------------------------------------------------------------------------
// PTX helpers
// ---------------------------------------------------------------------------
__device__ __forceinline__ unsigned smem_u32(const void* p) {
    unsigned a;
    asm("{ .reg .u64 t; cvta.to.shared.u64 t, %1; cvt.u32.u64 %0, t; }" : "=r"(a) : "l"(p));
    return a;
}

#define MBARRIER_INIT(addr, cnt) \
    asm volatile("mbarrier.init.shared.b64 [%0], %1;" :: "r"((unsigned)(addr)), "r"((unsigned)(cnt)) : "memory")

#define MBARRIER_EXPECT_TX(addr, bytes) \
    asm volatile("mbarrier.arrive.expect_tx.shared.b64 _, [%0], %1;" :: "r"((unsigned)(addr)), "r"((unsigned)(bytes)) : "memory")

#define MBARRIER_ARRIVE(addr) \
    asm volatile("mbarrier.arrive.shared.b64 _, [%0];" :: "r"((unsigned)(addr)) : "memory")

#define MBARRIER_WAIT_PARITY(addr, parity) do {                                    \
    unsigned _m = (unsigned)(addr); unsigned _p = (unsigned)(parity); unsigned _d; \
    asm volatile("{\n\t.reg .pred p;\n\t"                                          \
        "mbarrier.try_wait.parity.acquire.cta.shared::cta.b64 p, [%1], %2;\n\t"    \
        "selp.b32 %0, 1, 0, p;\n\t}"                                               \
        : "=r"(_d) : "r"(_m), "r"(_p) : "memory");                                 \
    if (!_d) {                                                                     \
        asm volatile("{\n\t.reg .pred P1;\n\t"                                     \
        "WL_%=:\n\t"                                                               \
        "mbarrier.try_wait.parity.acquire.cta.shared::cta.b64 P1, [%0], %1, 0x989680;\n\t" \
        "@P1 bra.uni WD_%=;\n\t"                                                   \
        "bra.uni WL_%=;\n\t"                                                       \
        "WD_%=:\n\t}" :: "r"(_m), "r"(_p) : "memory");                             \
    }                                                                              \
} while (0)

#define TMA_LOAD_2D(dst, map, x, y, mbar) \
    asm volatile("cp.async.bulk.tensor.2d.shared::cta.global.tile.mbarrier::complete_tx::bytes " \
        "[%0], [%1, {%2, %3}], [%4];" \
        :: "r"((unsigned)(dst)), "l"(map), "r"((int)(x)), "r"((int)(y)), "r"((unsigned)(mbar)) : "memory")

#define LDSM4(r, addr)                                                        \
    asm volatile("ldmatrix.sync.aligned.m8n8.x4.shared.b16 {%0,%1,%2,%3}, [%4];" \
        : "=r"((r)[0]), "=r"((r)[1]), "=r"((r)[2]), "=r"((r)[3]) : "r"(addr))

#define MMA_BF16(d, a, b)                                                     \
    asm volatile(                                                             \
        "mma.sync.aligned.m16n8k16.row.col.f32.bf16.bf16.f32 "                \
        "{%0,%1,%2,%3}, {%4,%5,%6,%7}, {%8,%9}, {%0,%1,%2,%3};"               \
        : "+f"((d)[0]), "+f"((d)[1]), "+f"((d)[2]), "+f"((d)[3])              \
        : "r"((a)[0]), "r"((a)[1]), "r"((a)[2]), "r"((a)[3]),                 \
          "r"((b)[0]), "r"((b)[1]))

// ---------------------------------------------------------------------------
// Mask dtype detection (bool vs int32)
// ---------------------------------------------------------------------------
__global__ void detect_mask_kernel(const unsigned char* m) {
    int i32 = 1;
    for (int i = 0; i < 256; ++i)
        if (m[i * 4 + 1] | m[i * 4 + 2] | m[i * 4 + 3]) { i32 = 0; break; }
    g_mask_i32 = i32;
}

__device__ __forceinline__ bool is_masked(const void* mask, int idx, int m_i32) {
    if (m_i32) return ((const int*)mask)[idx] != 0;
    return ((const unsigned char*)mask)[idx] != 0;
}

// ---------------------------------------------------------------------------
// Split fp32 -> (hi, lo) bf16 pair
// ---------------------------------------------------------------------------
__global__ __launch_bounds__(256) void split_bf16_kernel(const float* __restrict__ key) {
    size_t i = (size_t)blockIdx.x * 256 + threadIdx.x;
    float4 v0 = ((const float4*)key)[2 * i];
    float4 v1 = ((const float4*)key)[2 * i + 1];
    float v[8] = {v0.x, v0.y, v0.z, v0.w, v1.x, v1.y, v1.z, v1.w};
    __nv_bfloat16 h[8], l[8];
#pragma unroll
    for (int e = 0; e < 8; ++e) {
        h[e] = __float2bfloat16_rn(v[e]);
        l[e] = __float2bfloat16_rn(v[e] - __bfloat162float(h[e]));
    }
    ((uint4*)g_khi)[i] = *(const uint4*)h;
    ((uint4*)g_klo)[i] = *(const uint4*)l;
}

// ---------------------------------------------------------------------------
// kp[b,i,c] = key[b,i,:] . params[c,:]
// ---------------------------------------------------------------------------
__global__ __launch_bounds__(256) void compute_kp_kernel(const float* __restrict__ key,
                                                         const float* __restrict__ params) {
    __shared__ float sp[CDIST * DIM];
    int tid = threadIdx.x;
    for (int i = tid; i < CDIST * DIM; i += 256) sp[i] = params[i];
    __syncthreads();

    int warp = tid >> 5, lane = tid & 31;
    int row = blockIdx.x * 8 + warp;
    const float* krow = key + (size_t)row * DIM;
    float kr[16];
#pragma unroll
    for (int t = 0; t < 16; ++t) kr[t] = krow[lane + 32 * t];

    float* out = g_kp + (size_t)row * CDIST;
#pragma unroll 1
    for (int c = 0; c < CDIST; ++c) {
        const float* prow = sp + c * DIM;
        float acc = 0.f;
#pragma unroll
        for (int t = 0; t < 16; ++t) acc += kr[t] * prow[lane + 32 * t];
#pragma unroll
        for (int o = 16; o > 0; o >>= 1) acc += __shfl_xor_sync(0xFFFFFFFFu, acc, o);
        if (lane == 0) out[c] = acc;
    }
}

// ---------------------------------------------------------------------------
// Main GEMM: 3x-bf16 mma.sync, 4 warps of 64x64 (32 independent MMAs per
// pass per warp), TMA-fed 3-stage pipeline, triangular symmetric tiles.
// ---------------------------------------------------------------------------
__global__ __launch_bounds__(NTHREADS, 2) void attn_mma_kernel(
    const __grid_constant__ CUtensorMap mhi,
    const __grid_constant__ CUtensorMap mlo,
    const void* __restrict__ mask,
    float* __restrict__ out) {
    extern __shared__ char smem_raw[];
    unsigned sb_raw = smem_u32(smem_raw);
    unsigned sb = (sb_raw + 1023u) & ~1023u;
    char* smem_base = smem_raw + (sb - sb_raw);
    unsigned fullb = sb + PIPE_B;
    unsigned emptyb = fullb + NSTAGES * 8;

    int tid = threadIdx.x;
    int wid = tid >> 5;
    int lane = tid & 31;
    int lr = lane >> 2;
    int lc = lane & 3;
    int warp_m = wid & 1;    // 2 warps in M (64 rows each)
    int warp_n = wid >> 1;   // 2 warps in N (64 cols each)

    // triangular tile decode
    int t = blockIdx.x;
    int bi = 0;
    while (t >= NTILE - bi) { t -= NTILE - bi; ++bi; }
    int bj = bi + t;
    int b = blockIdx.y;
    int bL = b * LSEQ;
    int i0 = bi * TILE, j0 = bj * TILE;
    bool domirror = (bi != bj);

    if (tid == 0) {
#pragma unroll
        for (int s = 0; s < NSTAGES; ++s) {
            MBARRIER_INIT(fullb + s * 8, 1);
            MBARRIER_INIT(emptyb + s * 8, 4);           // one arrive per warp
        }
    }
    __syncthreads();

#define ISSUE(c)                                                              \
    do {                                                                      \
        int s_ = (c) % NSTAGES;                                               \
        unsigned st_ = sb + (unsigned)s_ * STAGE_B;                           \
        unsigned bar_ = fullb + s_ * 8;                                       \
        int k0_ = (c) * KCHUNK;                                               \
        MBARRIER_EXPECT_TX(bar_, STAGE_B);                                    \
        TMA_LOAD_2D(st_ + 0 * ARR_B, &mhi, k0_, bL + i0, bar_);               \
        TMA_LOAD_2D(st_ + 1 * ARR_B, &mlo, k0_, bL + i0, bar_);               \
        TMA_LOAD_2D(st_ + 2 * ARR_B, &mhi, k0_, bL + j0, bar_);               \
        TMA_LOAD_2D(st_ + 3 * ARR_B, &mlo, k0_, bL + j0, bar_);               \
    } while (0)

    if (tid == 0) {
        ISSUE(0); ISSUE(1); ISSUE(2);
    }

    float acc[4][8][4];   // mi x ni x frag — 128 regs
#pragma unroll
    for (int mi = 0; mi < 4; ++mi)
#pragma unroll
        for (int ni = 0; ni < 8; ++ni)
#pragma unroll
            for (int r = 0; r < 4; ++r) acc[mi][ni][r] = 0.f;

    // ldmatrix lane addressing (SW64-swizzled 64B rows)
    int row_a = warp_m * 64 + (lane & 15);
    unsigned xka = (unsigned)(((row_a >> 1) & 3) << 4);
    int row_b = warp_n * 64 + (lane & 7) + ((lane >> 4) << 3);
    unsigned xkb = (unsigned)(((row_b >> 1) & 3) << 4);
    unsigned ca0 = (unsigned)((lane >> 4) << 4);        // {0,16}
    unsigned cb0 = (unsigned)(((lane >> 3) & 1) << 4);  // {0,16}

#pragma unroll 1
    for (int c = 0; c < NCHUNK; ++c) {
        int s = c % NSTAGES;
        unsigned ph = (unsigned)((c / NSTAGES) & 1);
        MBARRIER_WAIT_PARITY(fullb + s * 8, ph);

        unsigned st = sb + (unsigned)s * STAGE_B;
        unsigned baseA = st + (unsigned)row_a * ROWB;
        unsigned baseB = st + 2 * ARR_B + (unsigned)row_b * ROWB;

#pragma unroll
        for (int ks = 0; ks < 2; ++ks) {
            unsigned ca = (ca0 | (unsigned)(ks << 5)) ^ xka;
            unsigned cb = (cb0 | (unsigned)(ks << 5)) ^ xkb;
            unsigned aAhi = baseA + ca;                 // + mi*1024; +ARR_B for lo
            unsigned aB = baseB + cb;                   // + p*1024;  +ARR_B for lo

            unsigned bh[16], bl[16];
            unsigned ah[4][4], al[4][4];
#pragma unroll
            for (int p = 0; p < 4; ++p) LDSM4(&bh[4 * p], aB + p * 1024);
#pragma unroll
            for (int p = 0; p < 4; ++p) LDSM4(&bl[4 * p], aB + ARR_B + p * 1024);
#pragma unroll
            for (int mi = 0; mi < 4; ++mi) LDSM4(ah[mi], aAhi + mi * 1024);

            // pass 1: 32 independent MMAs (ah x bh)
#pragma unroll
            for (int mi = 0; mi < 4; ++mi)
#pragma unroll
                for (int ni = 0; ni < 8; ++ni) MMA_BF16(acc[mi][ni], ah[mi], &bh[2 * ni]);

            // prefetch al while pass-1 drains
#pragma unroll
            for (int mi = 0; mi < 4; ++mi) LDSM4(al[mi], aAhi + ARR_B + mi * 1024);

            // pass 2: 32 independent MMAs (ah x bl)
#pragma unroll
            for (int mi = 0; mi < 4; ++mi)
#pragma unroll
                for (int ni = 0; ni < 8; ++ni) MMA_BF16(acc[mi][ni], ah[mi], &bl[2 * ni]);

            // pass 3: 32 independent MMAs (al x bh)
#pragma unroll
            for (int mi = 0; mi < 4; ++mi)
#pragma unroll
                for (int ni = 0; ni < 8; ++ni) MMA_BF16(acc[mi][ni], al[mi], &bh[2 * ni]);
        }

        if (lane == 0) MBARRIER_ARRIVE(emptyb + s * 8);
        if (tid == 0 && c + NSTAGES < NCHUNK) {
            MBARRIER_WAIT_PARITY(emptyb + s * 8, ph);
            ISSUE(c + NSTAGES);
        }
    }
    __syncthreads();   // stage memory now reusable for epilogue

    // ---- epilogue: 4 chunks of 32x32 per warp; banded kp bias fast path ----
    int m_i32 = g_mask_i32;
    float* tb = (float*)smem_base + wid * (32 * 33);

#pragma unroll 1
    for (int cch = 0; cch < 2; ++cch) {
        int jc0 = j0 + warp_n * 64 + cch * 32;
        unsigned mj = __ballot_sync(0xFFFFFFFFu, is_masked(mask, bL + jc0 + lane, m_i32));
        const float* kpM = g_kp + (size_t)(bL + jc0 + lane) * CDIST;

#pragma unroll 1
        for (int rch = 0; rch < 2; ++rch) {
            int ib0 = i0 + warp_m * 64 + rch * 32;
            unsigned mib = __ballot_sync(0xFFFFFFFFu, is_masked(mask, bL + ib0 + lane, m_i32));

#pragma unroll
            for (int mi2 = 0; mi2 < 2; ++mi2) {
                int mi = rch * 2 + mi2;
#pragma unroll
                for (int nn = 0; nn < 4; ++nn) {
                    int ni = cch * 4 + nn;
                    int r = mi2 * 16 + lr;
                    int cb = nn * 8 + lc * 2;
                    tb[r * 33 + cb]           = acc[mi][ni][0];
                    tb[r * 33 + cb + 1]       = acc[mi][ni][1];
                    tb[(r + 8) * 33 + cb]     = acc[mi][ni][2];
                    tb[(r + 8) * 33 + cb + 1] = acc[mi][ni][3];
                }
            }
            __syncwarp();

            int diff = jc0 - ib0;

            // normal orientation: row ir = ib0+lane, cols jc0..jc0+31
            {
                int ir = ib0 + lane;
                const float* kpR = g_kp + (size_t)(bL + ir) * CDIST;
                float v[32];
                if (diff >= 41 || diff <= -41) {
                    float kc = __ldg(kpR + (diff >= 41 ? 20 : 0));
#pragma unroll
                    for (int cc = 0; cc < 32; ++cc) {
                        float x = tb[lane * 33 + cc] + kc;
                        v[cc] = ((mj >> cc) & 1u) ? -1e20f : x;
                    }
                } else {
#pragma unroll
                    for (int cc = 0; cc < 32; ++cc) {
                        int dd = (jc0 + cc) - ir;
                        dd = min(CLIPD, max(-CLIPD, dd)) + CLIPD;
                        float x = tb[lane * 33 + cc] + __ldg(kpR + dd);
                        v[cc] = ((mj >> cc) & 1u) ? -1e20f : x;
                    }
                }
                float* op = out + (size_t)(bL + ir) * LSEQ + jc0;
#pragma unroll
                for (int p = 0; p < 8; ++p)
                    ((float4*)op)[p] = make_float4(v[4 * p], v[4 * p + 1], v[4 * p + 2], v[4 * p + 3]);
            }

            // mirrored orientation: row jr = jc0+lane, cols ib0..ib0+31
            if (domirror) {
                int jr = jc0 + lane;
                float v[32];
                if (diff >= 41 || diff <= -41) {
                    float kc = __ldg(kpM + (diff >= 41 ? 0 : 20));
#pragma unroll
                    for (int cc = 0; cc < 32; ++cc) {
                        float x = tb[cc * 33 + lane] + kc;
                        v[cc] = ((mib >> cc) & 1u) ? -1e20f : x;
                    }
                } else {
#pragma unroll
                    for (int cc = 0; cc < 32; ++cc) {
                        int dd = (ib0 + cc) - jr;
                        dd = min(CLIPD, max(-CLIPD, dd)) + CLIPD;
                        float x = tb[cc * 33 + lane] + __ldg(kpM + dd);
                        v[cc] = ((mib >> cc) & 1u) ? -1e20f : x;
                    }
                }
                float* op = out + (size_t)(bL + jr) * LSEQ + ib0;
#pragma unroll
                for (int p = 0; p < 8; ++p)
                    ((float4*)op)[p] = make_float4(v[4 * p], v[4 * p + 1], v[4 * p + 2], v[4 * p + 3]);
            }
            __syncwarp();
        }
    }
}

// ---------------------------------------------------------------------------
// Row softmax (in place)
// ---------------------------------------------------------------------------
__global__ __launch_bounds__(256) void softmax_rows_kernel(float* __restrict__ out) {
    __shared__ float red[8];
    int t = threadIdx.x;
    float* p = out + (size_t)blockIdx.x * LSEQ + t * 8;
    float4 v0 = *(const float4*)p;
    float4 v1 = *(const float4*)(p + 4);
    float v[8] = {v0.x, v0.y, v0.z, v0.w, v1.x, v1.y, v1.z, v1.w};

    float m = v[0];
#pragma unroll
    for (int i = 1; i < 8; ++i) m = fmaxf(m, v[i]);
#pragma unroll
    for (int o = 16; o > 0; o >>= 1) m = fmaxf(m, __shfl_xor_sync(0xFFFFFFFFu, m, o));
    if ((t & 31) == 0) red[t >> 5] = m;
    __syncthreads();
    float mm = red[0];
#pragma unroll
    for (int i = 1; i < 8; ++i) mm = fmaxf(mm, red[i]);
    __syncthreads();

    float e[8], s = 0.f;
#pragma unroll
    for (int i = 0; i < 8; ++i) { e[i] = expf(v[i] - mm); s += e[i]; }
#pragma unroll
    for (int o = 16; o > 0; o >>= 1) s += __shfl_xor_sync(0xFFFFFFFFu, s, o);
    if ((t & 31) == 0) red[t >> 5] = s;
    __syncthreads();
    float tot = 0.f;
#pragma unroll
    for (int i = 0; i < 8; ++i) tot += red[i];
    float inv = 1.0f / tot;

    *(float4*)p = make_float4(e[0] * inv, e[1] * inv, e[2] * inv, e[3] * inv);
    *(float4*)(p + 4) = make_float4(e[4] * inv, e[5] * inv, e[6] * inv, e[7] * inv);
}

// ---------------------------------------------------------------------------
typedef CUresult (*PFN_encodeTiled)(CUtensorMap*, CUtensorMapDataType, cuuint32_t, void*,
                                    const cuuint64_t*, const cuuint64_t*, const cuuint32_t*,
                                    const cuuint32_t*, CUtensorMapInterleave, CUtensorMapSwizzle,
                                    CUtensorMapL2promotion, CUtensorMapFloatOOBfill);

extern "C" void kernel_launch(void* const* d_in, const int* in_sizes, int n_in,
                              void* d_out, int out_size) {
    const float* key = (const float*)d_in[0];
    const void* mask = d_in[1];
    const float* params = (const float*)d_in[2];
    float* out = (float*)d_out;

    void* khi_ptr = nullptr;
    void* klo_ptr = nullptr;
    cudaGetSymbolAddress(&khi_ptr, g_khi);
    cudaGetSymbolAddress(&klo_ptr, g_klo);

    void* fn = nullptr;
    cudaDriverEntryPointQueryResult qr;
    cudaGetDriverEntryPointByVersion("cuTensorMapEncodeTiled", &fn, 12000,
                                     cudaEnableDefault, &qr);
    PFN_encodeTiled enc = (PFN_encodeTiled)fn;

    CUtensorMap mhi, mlo;
    cuuint64_t dims[2] = {DIM, (cuuint64_t)BATCH * LSEQ};
    cuuint64_t strides[1] = {DIM * sizeof(__nv_bfloat16)};
    cuuint32_t box[2] = {KCHUNK, 128};
    cuuint32_t estr[2] = {1, 1};
    enc(&mhi, CU_TENSOR_MAP_DATA_TYPE_BFLOAT16, 2, khi_ptr, dims, strides, box, estr,
        CU_TENSOR_MAP_INTERLEAVE_NONE, CU_TENSOR_MAP_SWIZZLE_64B,
        CU_TENSOR_MAP_L2_PROMOTION_L2_128B, CU_TENSOR_MAP_FLOAT_OOB_FILL_NONE);
    enc(&mlo, CU_TENSOR_MAP_DATA_TYPE_BFLOAT16, 2, klo_ptr, dims, strides, box, estr,
        CU_TENSOR_MAP_INTERLEAVE_NONE, CU_TENSOR_MAP_SWIZZLE_64B,
        CU_TENSOR_MAP_L2_PROMOTION_L2_128B, CU_TENSOR_MAP_FLOAT_OOB_FILL_NONE);

    cudaFuncSetAttribute(attn_mma_kernel, cudaFuncAttributeMaxDynamicSharedMemorySize, SMEM_BYTES);

    detect_mask_kernel<<<1, 1>>>((const unsigned char*)mask);
    split_bf16_kernel<<<BATCH * LSEQ * DIM / 8 / 256, 256>>>(key);
    compute_kp_kernel<<<BATCH * LSEQ / 8, 256>>>(key, params);
    attn_mma_kernel<<<dim3(NPAIRS, BATCH), NTHREADS, SMEM_BYTES>>>(mhi, mlo, mask, out);
    softmax_rows_kernel<<<BATCH * LSEQ, 256>>>(out);
}

// round 12
// speedup vs baseline: 3.1282x; 3.1282x over previous
#include <cuda_runtime.h>
#include <cuda.h>
#include <cuda_bf16.h>
#include <math.h>

// ---------------------------------------------------------------------------
// Problem constants
// ---------------------------------------------------------------------------
#define BATCH 16
#define LSEQ  2048
#define DIM   512
#define CDIST 21
#define CLIPD 10

// GEMM tiling (R8 configuration — best measured)
#define TILE 128
#define NTILE (LSEQ / TILE)      // 16
#define NPAIRS (NTILE * (NTILE + 1) / 2)   // 136
#define KCHUNK 32                // bf16 K elems per TMA stage (64 B rows)
#define NCHUNK (DIM / KCHUNK)    // 16
#define NSTAGES 3
#define ROWB 64
#define ARR_B (128 * ROWB)       // 8192 B
#define STAGE_B (4 * ARR_B)      // 32768 B (Ahi, Alo, Bhi, Blo)
#define PIPE_B (NSTAGES * STAGE_B)          // 98304
#define SMEM_BYTES (PIPE_B + 64 + 1024)

// ---------------------------------------------------------------------------
// Device scratch
// ---------------------------------------------------------------------------
__device__ __align__(1024) __nv_bfloat16 g_khi[BATCH * LSEQ * DIM];
__device__ __align__(1024) __nv_bfloat16 g_klo[BATCH * LSEQ * DIM];
__device__ float g_kp[BATCH * LSEQ * CDIST];
__device__ int   g_mask_i32;

// ---------------------------------------------------------------------------
// PTX helpers
// ---------------------------------------------------------------------------
__device__ __forceinline__ unsigned smem_u32(const void* p) {
    unsigned a;
    asm("{ .reg .u64 t; cvta.to.shared.u64 t, %1; cvt.u32.u64 %0, t; }" : "=r"(a) : "l"(p));
    return a;
}

#define MBARRIER_INIT(addr, cnt) \
    asm volatile("mbarrier.init.shared.b64 [%0], %1;" :: "r"((unsigned)(addr)), "r"((unsigned)(cnt)) : "memory")

#define MBARRIER_EXPECT_TX(addr, bytes) \
    asm volatile("mbarrier.arrive.expect_tx.shared.b64 _, [%0], %1;" :: "r"((unsigned)(addr)), "r"((unsigned)(bytes)) : "memory")

#define MBARRIER_ARRIVE(addr) \
    asm volatile("mbarrier.arrive.shared.b64 _, [%0];" :: "r"((unsigned)(addr)) : "memory")

#define MBARRIER_WAIT_PARITY(addr, parity) do {                                    \
    unsigned _m = (unsigned)(addr); unsigned _p = (unsigned)(parity); unsigned _d; \
    asm volatile("{\n\t.reg .pred p;\n\t"                                          \
        "mbarrier.try_wait.parity.acquire.cta.shared::cta.b64 p, [%1], %2;\n\t"    \
        "selp.b32 %0, 1, 0, p;\n\t}"                                               \
        : "=r"(_d) : "r"(_m), "r"(_p) : "memory");                                 \
    if (!_d) {                                                                     \
        asm volatile("{\n\t.reg .pred P1;\n\t"                                     \
        "WL_%=:\n\t"                                                               \
        "mbarrier.try_wait.parity.acquire.cta.shared::cta.b64 P1, [%0], %1, 0x989680;\n\t" \
        "@P1 bra.uni WD_%=;\n\t"                                                   \
        "bra.uni WL_%=;\n\t"                                                       \
        "WD_%=:\n\t}" :: "r"(_m), "r"(_p) : "memory");                             \
    }                                                                              \
} while (0)

#define TMA_LOAD_2D(dst, map, x, y, mbar) \
    asm volatile("cp.async.bulk.tensor.2d.shared::cta.global.tile.mbarrier::complete_tx::bytes " \
        "[%0], [%1, {%2, %3}], [%4];" \
        :: "r"((unsigned)(dst)), "l"(map), "r"((int)(x)), "r"((int)(y)), "r"((unsigned)(mbar)) : "memory")

#define LDSM4(r, addr)                                                        \
    asm volatile("ldmatrix.sync.aligned.m8n8.x4.shared.b16 {%0,%1,%2,%3}, [%4];" \
        : "=r"((r)[0]), "=r"((r)[1]), "=r"((r)[2]), "=r"((r)[3]) : "r"(addr))

#define MMA_BF16(d, a, b)                                                     \
    asm volatile(                                                             \
        "mma.sync.aligned.m16n8k16.row.col.f32.bf16.bf16.f32 "                \
        "{%0,%1,%2,%3}, {%4,%5,%6,%7}, {%8,%9}, {%0,%1,%2,%3};"               \
        : "+f"((d)[0]), "+f"((d)[1]), "+f"((d)[2]), "+f"((d)[3])              \
        : "r"((a)[0]), "r"((a)[1]), "r"((a)[2]), "r"((a)[3]),                 \
          "r"((b)[0]), "r"((b)[1]))

// ---------------------------------------------------------------------------
// Mask dtype detection (bool vs int32)
// ---------------------------------------------------------------------------
__global__ void detect_mask_kernel(const unsigned char* m) {
    int i32 = 1;
    for (int i = 0; i < 256; ++i)
        if (m[i * 4 + 1] | m[i * 4 + 2] | m[i * 4 + 3]) { i32 = 0; break; }
    g_mask_i32 = i32;
}

__device__ __forceinline__ bool is_masked(const void* mask, int idx, int m_i32) {
    if (m_i32) return ((const int*)mask)[idx] != 0;
    return ((const unsigned char*)mask)[idx] != 0;
}

// ---------------------------------------------------------------------------
// FUSED prep: one pass over key.
//   - split fp32 -> (hi, lo) bf16 pair (hi = bf16(v), lo = bf16(v - hi))
//   - kp[b,i,c] = key[b,i,:] . params[c,:]
// One warp per row; params staged in SMEM once per block.
// ---------------------------------------------------------------------------
__global__ __launch_bounds__(256) void prep_kernel(const float* __restrict__ key,
                                                   const float* __restrict__ params) {
    __shared__ float sp[CDIST * DIM];
    int tid = threadIdx.x;
    for (int i = tid; i < CDIST * DIM; i += 256) sp[i] = params[i];
    __syncthreads();

    int warp = tid >> 5, lane = tid & 31;
    int row = blockIdx.x * 8 + warp;
    const float* krow = key + (size_t)row * DIM;

    float kr[16];
#pragma unroll
    for (int t = 0; t < 16; ++t) kr[t] = krow[lane + 32 * t];

    // split -> bf16 hi/lo (coalesced 2B stores, 64B per warp-step)
    __nv_bfloat16* hrow = g_khi + (size_t)row * DIM;
    __nv_bfloat16* lrow = g_klo + (size_t)row * DIM;
#pragma unroll
    for (int t = 0; t < 16; ++t) {
        float v = kr[t];
        __nv_bfloat16 h = __float2bfloat16_rn(v);
        __nv_bfloat16 l = __float2bfloat16_rn(v - __bfloat162float(h));
        hrow[lane + 32 * t] = h;
        lrow[lane + 32 * t] = l;
    }

    // kp dot products
    float* out = g_kp + (size_t)row * CDIST;
#pragma unroll 1
    for (int c = 0; c < CDIST; ++c) {
        const float* prow = sp + c * DIM;
        float acc = 0.f;
#pragma unroll
        for (int t = 0; t < 16; ++t) acc += kr[t] * prow[lane + 32 * t];
#pragma unroll
        for (int o = 16; o > 0; o >>= 1) acc += __shfl_xor_sync(0xFFFFFFFFu, acc, o);
        if (lane == 0) out[c] = acc;
    }
}

// ---------------------------------------------------------------------------
// Main GEMM (R8 config): 3x-bf16 mma.sync + ldmatrix, TMA-fed 3-stage
// pipeline, 8 warps of 64x32, 3 passes of 16 independent MMAs,
// triangular symmetric tiles, banded bias + mask epilogue.
// ---------------------------------------------------------------------------
__global__ __launch_bounds__(256, 2) void attn_mma_kernel(
    const __grid_constant__ CUtensorMap mhi,
    const __grid_constant__ CUtensorMap mlo,
    const void* __restrict__ mask,
    float* __restrict__ out) {
    extern __shared__ char smem_raw[];
    unsigned sb_raw = smem_u32(smem_raw);
    unsigned sb = (sb_raw + 1023u) & ~1023u;
    char* smem_base = smem_raw + (sb - sb_raw);
    unsigned fullb = sb + PIPE_B;
    unsigned emptyb = fullb + NSTAGES * 8;

    int tid = threadIdx.x;
    int wid = tid >> 5;
    int lane = tid & 31;
    int lr = lane >> 2;
    int lc = lane & 3;
    int warp_m = wid & 1;
    int warp_n = wid >> 1;

    int t = blockIdx.x;
    int bi = 0;
    while (t >= NTILE - bi) { t -= NTILE - bi; ++bi; }
    int bj = bi + t;
    int b = blockIdx.y;
    int bL = b * LSEQ;
    int i0 = bi * TILE, j0 = bj * TILE;
    bool domirror = (bi != bj);

    if (tid == 0) {
#pragma unroll
        for (int s = 0; s < NSTAGES; ++s) {
            MBARRIER_INIT(fullb + s * 8, 1);
            MBARRIER_INIT(emptyb + s * 8, 8);
        }
    }
    __syncthreads();

#define ISSUE(c)                                                              \
    do {                                                                      \
        int s_ = (c) % NSTAGES;                                               \
        unsigned st_ = sb + (unsigned)s_ * STAGE_B;                           \
        unsigned bar_ = fullb + s_ * 8;                                       \
        int k0_ = (c) * KCHUNK;                                               \
        MBARRIER_EXPECT_TX(bar_, STAGE_B);                                    \
        TMA_LOAD_2D(st_ + 0 * ARR_B, &mhi, k0_, bL + i0, bar_);               \
        TMA_LOAD_2D(st_ + 1 * ARR_B, &mlo, k0_, bL + i0, bar_);               \
        TMA_LOAD_2D(st_ + 2 * ARR_B, &mhi, k0_, bL + j0, bar_);               \
        TMA_LOAD_2D(st_ + 3 * ARR_B, &mlo, k0_, bL + j0, bar_);               \
    } while (0)

    if (tid == 0) {
        ISSUE(0); ISSUE(1); ISSUE(2);
    }

    float acc[4][4][4];
#pragma unroll
    for (int mi = 0; mi < 4; ++mi)
#pragma unroll
        for (int ni = 0; ni < 4; ++ni)
#pragma unroll
            for (int r = 0; r < 4; ++r) acc[mi][ni][r] = 0.f;

    int row_a = warp_m * 64 + (lane & 15);
    unsigned xka = (unsigned)(((row_a >> 1) & 3) << 4);
    int row_b = warp_n * 32 + (lane & 7) + ((lane >> 4) << 3);
    unsigned xkb = (unsigned)(((row_b >> 1) & 3) << 4);
    unsigned ca0 = (unsigned)((lane >> 4) << 4);
    unsigned cb0 = (unsigned)(((lane >> 3) & 1) << 4);

#pragma unroll 1
    for (int c = 0; c < NCHUNK; ++c) {
        int s = c % NSTAGES;
        unsigned ph = (unsigned)((c / NSTAGES) & 1);
        MBARRIER_WAIT_PARITY(fullb + s * 8, ph);

        unsigned st = sb + (unsigned)s * STAGE_B;
        unsigned baseA = st + (unsigned)row_a * ROWB;
        unsigned baseB = st + 2 * ARR_B + (unsigned)row_b * ROWB;

#pragma unroll
        for (int ks = 0; ks < 2; ++ks) {
            unsigned ca = (ca0 | (unsigned)(ks << 5)) ^ xka;
            unsigned cb = (cb0 | (unsigned)(ks << 5)) ^ xkb;
            unsigned aAhi = baseA + ca;
            unsigned aB = baseB + cb;

            unsigned bh[8], bl[8];
            unsigned ah[4][4], al[4][4];
            LDSM4(&bh[0], aB);
            LDSM4(&bh[4], aB + 1024);
            LDSM4(&bl[0], aB + ARR_B);
            LDSM4(&bl[4], aB + ARR_B + 1024);
#pragma unroll
            for (int mi = 0; mi < 4; ++mi) LDSM4(ah[mi], aAhi + mi * 1024);

#pragma unroll
            for (int mi = 0; mi < 4; ++mi)
#pragma unroll
                for (int ni = 0; ni < 4; ++ni) MMA_BF16(acc[mi][ni], ah[mi], &bh[2 * ni]);

#pragma unroll
            for (int mi = 0; mi < 4; ++mi) LDSM4(al[mi], aAhi + ARR_B + mi * 1024);

#pragma unroll
            for (int mi = 0; mi < 4; ++mi)
#pragma unroll
                for (int ni = 0; ni < 4; ++ni) MMA_BF16(acc[mi][ni], ah[mi], &bl[2 * ni]);

#pragma unroll
            for (int mi = 0; mi < 4; ++mi)
#pragma unroll
                for (int ni = 0; ni < 4; ++ni) MMA_BF16(acc[mi][ni], al[mi], &bh[2 * ni]);
        }

        if (lane == 0) MBARRIER_ARRIVE(emptyb + s * 8);
        if (tid == 0 && c + NSTAGES < NCHUNK) {
            MBARRIER_WAIT_PARITY(emptyb + s * 8, ph);
            ISSUE(c + NSTAGES);
        }
    }
    __syncthreads();

    // ---- epilogue ----
    int m_i32 = g_mask_i32;
    float* tb = (float*)smem_base + wid * (32 * 33);
    int jc0 = j0 + warp_n * 32;
    unsigned mj = __ballot_sync(0xFFFFFFFFu, is_masked(mask, bL + jc0 + lane, m_i32));
    const float* kpM = g_kp + (size_t)(bL + jc0 + lane) * CDIST;

#pragma unroll 1
    for (int ch = 0; ch < 2; ++ch) {
        int ib0 = i0 + warp_m * 64 + ch * 32;
        unsigned mib = __ballot_sync(0xFFFFFFFFu, is_masked(mask, bL + ib0 + lane, m_i32));

#pragma unroll
        for (int mi2 = 0; mi2 < 2; ++mi2) {
            int mi = ch * 2 + mi2;
#pragma unroll
            for (int ni = 0; ni < 4; ++ni) {
                int r = mi2 * 16 + lr;
                int cb = ni * 8 + lc * 2;
                tb[r * 33 + cb]           = acc[mi][ni][0];
                tb[r * 33 + cb + 1]       = acc[mi][ni][1];
                tb[(r + 8) * 33 + cb]     = acc[mi][ni][2];
                tb[(r + 8) * 33 + cb + 1] = acc[mi][ni][3];
            }
        }
        __syncwarp();

        int diff = jc0 - ib0;

        {
            int ir = ib0 + lane;
            const float* kpR = g_kp + (size_t)(bL + ir) * CDIST;
            float v[32];
            if (diff >= 41 || diff <= -41) {
                float kc = __ldg(kpR + (diff >= 41 ? 20 : 0));
#pragma unroll
                for (int cc = 0; cc < 32; ++cc) {
                    float x = tb[lane * 33 + cc] + kc;
                    v[cc] = ((mj >> cc) & 1u) ? -1e20f : x;
                }
            } else {
#pragma unroll
                for (int cc = 0; cc < 32; ++cc) {
                    int dd = (jc0 + cc) - ir;
                    dd = min(CLIPD, max(-CLIPD, dd)) + CLIPD;
                    float x = tb[lane * 33 + cc] + __ldg(kpR + dd);
                    v[cc] = ((mj >> cc) & 1u) ? -1e20f : x;
                }
            }
            float* op = out + (size_t)(bL + ir) * LSEQ + jc0;
#pragma unroll
            for (int p = 0; p < 8; ++p)
                ((float4*)op)[p] = make_float4(v[4 * p], v[4 * p + 1], v[4 * p + 2], v[4 * p + 3]);
        }

        if (domirror) {
            int jr = jc0 + lane;
            float v[32];
            if (diff >= 41 || diff <= -41) {
                float kc = __ldg(kpM + (diff >= 41 ? 0 : 20));
#pragma unroll
                for (int cc = 0; cc < 32; ++cc) {
                    float x = tb[cc * 33 + lane] + kc;
                    v[cc] = ((mib >> cc) & 1u) ? -1e20f : x;
                }
            } else {
#pragma unroll
                for (int cc = 0; cc < 32; ++cc) {
                    int dd = (ib0 + cc) - jr;
                    dd = min(CLIPD, max(-CLIPD, dd)) + CLIPD;
                    float x = tb[cc * 33 + lane] + __ldg(kpM + dd);
                    v[cc] = ((mib >> cc) & 1u) ? -1e20f : x;
                }
            }
            float* op = out + (size_t)(bL + jr) * LSEQ + ib0;
#pragma unroll
            for (int p = 0; p < 8; ++p)
                ((float4*)op)[p] = make_float4(v[4 * p], v[4 * p + 1], v[4 * p + 2], v[4 * p + 3]);
        }
        __syncwarp();
    }
}

// ---------------------------------------------------------------------------
// Row softmax (in place) — hardware __expf
// ---------------------------------------------------------------------------
__global__ __launch_bounds__(256) void softmax_rows_kernel(float* __restrict__ out) {
    __shared__ float red[8];
    int t = threadIdx.x;
    float* p = out + (size_t)blockIdx.x * LSEQ + t * 8;
    float4 v0 = *(const float4*)p;
    float4 v1 = *(const float4*)(p + 4);
    float v[8] = {v0.x, v0.y, v0.z, v0.w, v1.x, v1.y, v1.z, v1.w};

    float m = v[0];
#pragma unroll
    for (int i = 1; i < 8; ++i) m = fmaxf(m, v[i]);
#pragma unroll
    for (int o = 16; o > 0; o >>= 1) m = fmaxf(m, __shfl_xor_sync(0xFFFFFFFFu, m, o));
    if ((t & 31) == 0) red[t >> 5] = m;
    __syncthreads();
    float mm = red[0];
#pragma unroll
    for (int i = 1; i < 8; ++i) mm = fmaxf(mm, red[i]);
    __syncthreads();

    float e[8], s = 0.f;
#pragma unroll
    for (int i = 0; i < 8; ++i) { e[i] = __expf(v[i] - mm); s += e[i]; }
#pragma unroll
    for (int o = 16; o > 0; o >>= 1) s += __shfl_xor_sync(0xFFFFFFFFu, s, o);
    if ((t & 31) == 0) red[t >> 5] = s;
    __syncthreads();
    float tot = 0.f;
#pragma unroll
    for (int i = 0; i < 8; ++i) tot += red[i];
    float inv = 1.0f / tot;

    *(float4*)p = make_float4(e[0] * inv, e[1] * inv, e[2] * inv, e[3] * inv);
    *(float4*)(p + 4) = make_float4(e[4] * inv, e[5] * inv, e[6] * inv, e[7] * inv);
}

// ---------------------------------------------------------------------------
typedef CUresult (*PFN_encodeTiled)(CUtensorMap*, CUtensorMapDataType, cuuint32_t, void*,
                                    const cuuint64_t*, const cuuint64_t*, const cuuint32_t*,
                                    const cuuint32_t*, CUtensorMapInterleave, CUtensorMapSwizzle,
                                    CUtensorMapL2promotion, CUtensorMapFloatOOBfill);

extern "C" void kernel_launch(void* const* d_in, const int* in_sizes, int n_in,
                              void* d_out, int out_size) {
    const float* key = (const float*)d_in[0];
    const void* mask = d_in[1];
    const float* params = (const float*)d_in[2];
    float* out = (float*)d_out;

    void* khi_ptr = nullptr;
    void* klo_ptr = nullptr;
    cudaGetSymbolAddress(&khi_ptr, g_khi);
    cudaGetSymbolAddress(&klo_ptr, g_klo);

    void* fn = nullptr;
    cudaDriverEntryPointQueryResult qr;
    cudaGetDriverEntryPointByVersion("cuTensorMapEncodeTiled", &fn, 12000,
                                     cudaEnableDefault, &qr);
    PFN_encodeTiled enc = (PFN_encodeTiled)fn;

    CUtensorMap mhi, mlo;
    cuuint64_t dims[2] = {DIM, (cuuint64_t)BATCH * LSEQ};
    cuuint64_t strides[1] = {DIM * sizeof(__nv_bfloat16)};
    cuuint32_t box[2] = {KCHUNK, 128};
    cuuint32_t estr[2] = {1, 1};
    enc(&mhi, CU_TENSOR_MAP_DATA_TYPE_BFLOAT16, 2, khi_ptr, dims, strides, box, estr,
        CU_TENSOR_MAP_INTERLEAVE_NONE, CU_TENSOR_MAP_SWIZZLE_64B,
        CU_TENSOR_MAP_L2_PROMOTION_L2_128B, CU_TENSOR_MAP_FLOAT_OOB_FILL_NONE);
    enc(&mlo, CU_TENSOR_MAP_DATA_TYPE_BFLOAT16, 2, klo_ptr, dims, strides, box, estr,
        CU_TENSOR_MAP_INTERLEAVE_NONE, CU_TENSOR_MAP_SWIZZLE_64B,
        CU_TENSOR_MAP_L2_PROMOTION_L2_128B, CU_TENSOR_MAP_FLOAT_OOB_FILL_NONE);

    cudaFuncSetAttribute(attn_mma_kernel, cudaFuncAttributeMaxDynamicSharedMemorySize, SMEM_BYTES);

    detect_mask_kernel<<<1, 1>>>((const unsigned char*)mask);
    prep_kernel<<<BATCH * LSEQ / 8, 256>>>(key, params);
    attn_mma_kernel<<<dim3(NPAIRS, BATCH), 256, SMEM_BYTES>>>(mhi, mlo, mask, out);
    softmax_rows_kernel<<<BATCH * LSEQ, 256>>>(out);
}

// round 14
// speedup vs baseline: 3.2414x; 1.0362x over previous
#include <cuda_runtime.h>
#include <cuda.h>
#include <cuda_bf16.h>
#include <math.h>

// ---------------------------------------------------------------------------
// Problem constants
// ---------------------------------------------------------------------------
#define BATCH 16
#define LSEQ  2048
#define DIM   512
#define CDIST 21
#define CLIPD 10

// GEMM tiling (R8/R12 configuration — best measured)
#define TILE 128
#define NTILE (LSEQ / TILE)      // 16
#define NPAIRS (NTILE * (NTILE + 1) / 2)   // 136
#define KCHUNK 32                // bf16 K elems per TMA stage (64 B rows)
#define NCHUNK (DIM / KCHUNK)    // 16
#define NSTAGES 3
#define ROWB 64
#define ARR_B (128 * ROWB)       // 8192 B
#define STAGE_B (4 * ARR_B)      // 32768 B (Ahi, Alo, Bhi, Blo)
#define PIPE_B (NSTAGES * STAGE_B)          // 98304
#define SMEM_BYTES (PIPE_B + 64 + 1024)

// ---------------------------------------------------------------------------
// Device scratch
// ---------------------------------------------------------------------------
__device__ __align__(1024) __nv_bfloat16 g_khi[BATCH * LSEQ * DIM];
__device__ __align__(1024) __nv_bfloat16 g_klo[BATCH * LSEQ * DIM];
__device__ float g_kp[BATCH * LSEQ * CDIST];
__device__ int   g_mask_i32;

// ---------------------------------------------------------------------------
// PTX helpers
// ---------------------------------------------------------------------------
__device__ __forceinline__ unsigned smem_u32(const void* p) {
    unsigned a;
    asm("{ .reg .u64 t; cvta.to.shared.u64 t, %1; cvt.u32.u64 %0, t; }" : "=r"(a) : "l"(p));
    return a;
}

#define MBARRIER_INIT(addr, cnt) \
    asm volatile("mbarrier.init.shared.b64 [%0], %1;" :: "r"((unsigned)(addr)), "r"((unsigned)(cnt)) : "memory")

#define MBARRIER_EXPECT_TX(addr, bytes) \
    asm volatile("mbarrier.arrive.expect_tx.shared.b64 _, [%0], %1;" :: "r"((unsigned)(addr)), "r"((unsigned)(bytes)) : "memory")

#define MBARRIER_ARRIVE(addr) \
    asm volatile("mbarrier.arrive.shared.b64 _, [%0];" :: "r"((unsigned)(addr)) : "memory")

#define MBARRIER_WAIT_PARITY(addr, parity) do {                                    \
    unsigned _m = (unsigned)(addr); unsigned _p = (unsigned)(parity); unsigned _d; \
    asm volatile("{\n\t.reg .pred p;\n\t"                                          \
        "mbarrier.try_wait.parity.acquire.cta.shared::cta.b64 p, [%1], %2;\n\t"    \
        "selp.b32 %0, 1, 0, p;\n\t}"                                               \
        : "=r"(_d) : "r"(_m), "r"(_p) : "memory");                                 \
    if (!_d) {                                                                     \
        asm volatile("{\n\t.reg .pred P1;\n\t"                                     \
        "WL_%=:\n\t"                                                               \
        "mbarrier.try_wait.parity.acquire.cta.shared::cta.b64 P1, [%0], %1, 0x989680;\n\t" \
        "@P1 bra.uni WD_%=;\n\t"                                                   \
        "bra.uni WL_%=;\n\t"                                                       \
        "WD_%=:\n\t}" :: "r"(_m), "r"(_p) : "memory");                             \
    }                                                                              \
} while (0)

#define TMA_LOAD_2D(dst, map, x, y, mbar) \
    asm volatile("cp.async.bulk.tensor.2d.shared::cta.global.tile.mbarrier::complete_tx::bytes " \
        "[%0], [%1, {%2, %3}], [%4];" \
        :: "r"((unsigned)(dst)), "l"(map), "r"((int)(x)), "r"((int)(y)), "r"((unsigned)(mbar)) : "memory")

#define LDSM4(r, addr)                                                        \
    asm volatile("ldmatrix.sync.aligned.m8n8.x4.shared.b16 {%0,%1,%2,%3}, [%4];" \
        : "=r"((r)[0]), "=r"((r)[1]), "=r"((r)[2]), "=r"((r)[3]) : "r"(addr))

#define MMA_BF16(d, a, b)                                                     \
    asm volatile(                                                             \
        "mma.sync.aligned.m16n8k16.row.col.f32.bf16.bf16.f32 "                \
        "{%0,%1,%2,%3}, {%4,%5,%6,%7}, {%8,%9}, {%0,%1,%2,%3};"               \
        : "+f"((d)[0]), "+f"((d)[1]), "+f"((d)[2]), "+f"((d)[3])              \
        : "r"((a)[0]), "r"((a)[1]), "r"((a)[2]), "r"((a)[3]),                 \
          "r"((b)[0]), "r"((b)[1]))

// ---------------------------------------------------------------------------
// Mask dtype detection (bool vs int32) — parallel, one block
// ---------------------------------------------------------------------------
__global__ __launch_bounds__(256) void detect_mask_kernel(const unsigned char* m) {
    int tid = threadIdx.x;
    int hit = (m[tid * 4 + 1] | m[tid * 4 + 2] | m[tid * 4 + 3]) != 0;
    int any = __syncthreads_or(hit);
    if (tid == 0) g_mask_i32 = (any == 0);
}

__device__ __forceinline__ bool is_masked(const void* mask, int idx, int m_i32) {
    if (m_i32) return ((const int*)mask)[idx] != 0;
    return ((const unsigned char*)mask)[idx] != 0;
}

__device__ __forceinline__ unsigned pack_bf16x2(float a, float b) {
    __nv_bfloat162 t = __floats2bfloat162_rn(a, b);   // .x=a (low), .y=b (high)
    return *reinterpret_cast<unsigned*>(&t);
}

// ---------------------------------------------------------------------------
// FUSED prep (vectorized): one pass over key.
//   - split fp32 -> (hi, lo) bf16 (float4 loads, uint2 bf16x4 stores)
//   - kp[b,i,c] = key[b,i,:] . params[c,:] (LDS.128, ILP'd butterfly)
// One warp per row.
// ---------------------------------------------------------------------------
__global__ __launch_bounds__(256) void prep_kernel(const float* __restrict__ key,
                                                   const float* __restrict__ params) {
    __shared__ float sp[CDIST * DIM];
    int tid = threadIdx.x;
    for (int i = tid; i < CDIST * DIM / 4; i += 256)
        ((float4*)sp)[i] = ((const float4*)params)[i];
    __syncthreads();

    int warp = tid >> 5, lane = tid & 31;
    int row = blockIdx.x * 8 + warp;

    // vectorized load: 4 float4 per thread (elements 4*(lane+32t) .. +3)
    const float4* krow4 = (const float4*)(key + (size_t)row * DIM);
    float4 kr[4];
#pragma unroll
    for (int t = 0; t < 4; ++t) kr[t] = krow4[lane + 32 * t];

    // split -> bf16 hi/lo, packed 8B stores
    uint2* hrow = (uint2*)(g_khi + (size_t)row * DIM);
    uint2* lrow = (uint2*)(g_klo + (size_t)row * DIM);
#pragma unroll
    for (int t = 0; t < 4; ++t) {
        float4 v = kr[t];
        float hx = __bfloat162float(__float2bfloat16_rn(v.x));
        float hy = __bfloat162float(__float2bfloat16_rn(v.y));
        float hz = __bfloat162float(__float2bfloat16_rn(v.z));
        float hw = __bfloat162float(__float2bfloat16_rn(v.w));
        uint2 hp, lp;
        hp.x = pack_bf16x2(hx, hy);
        hp.y = pack_bf16x2(hz, hw);
        lp.x = pack_bf16x2(v.x - hx, v.y - hy);
        lp.y = pack_bf16x2(v.z - hz, v.w - hw);
        hrow[lane + 32 * t] = hp;
        lrow[lane + 32 * t] = lp;
    }

    // kp: all 21 dot products with ILP, then interleaved butterfly
    float acc[CDIST];
    const float4* sp4 = (const float4*)sp;
#pragma unroll
    for (int c = 0; c < CDIST; ++c) {
        float a = 0.f;
#pragma unroll
        for (int t = 0; t < 4; ++t) {
            float4 p = sp4[c * (DIM / 4) + lane + 32 * t];
            a += kr[t].x * p.x + kr[t].y * p.y + kr[t].z * p.z + kr[t].w * p.w;
        }
        acc[c] = a;
    }
#pragma unroll
    for (int o = 16; o > 0; o >>= 1)
#pragma unroll
        for (int c = 0; c < CDIST; ++c)
            acc[c] += __shfl_xor_sync(0xFFFFFFFFu, acc[c], o);

    if (lane == 0) {
        float* out = g_kp + (size_t)row * CDIST;
#pragma unroll
        for (int c = 0; c < CDIST; ++c) out[c] = acc[c];
    }
}

// ---------------------------------------------------------------------------
// Main GEMM (R8 config): 3x-bf16 mma.sync + ldmatrix, TMA-fed 3-stage
// pipeline, 8 warps of 64x32, 3 passes of 16 independent MMAs,
// triangular symmetric tiles, banded bias + mask epilogue.
// ---------------------------------------------------------------------------
__global__ __launch_bounds__(256, 2) void attn_mma_kernel(
    const __grid_constant__ CUtensorMap mhi,
    const __grid_constant__ CUtensorMap mlo,
    const void* __restrict__ mask,
    float* __restrict__ out) {
    extern __shared__ char smem_raw[];
    unsigned sb_raw = smem_u32(smem_raw);
    unsigned sb = (sb_raw + 1023u) & ~1023u;
    char* smem_base = smem_raw + (sb - sb_raw);
    unsigned fullb = sb + PIPE_B;
    unsigned emptyb = fullb + NSTAGES * 8;

    int tid = threadIdx.x;
    int wid = tid >> 5;
    int lane = tid & 31;
    int lr = lane >> 2;
    int lc = lane & 3;
    int warp_m = wid & 1;
    int warp_n = wid >> 1;

    int t = blockIdx.x;
    int bi = 0;
    while (t >= NTILE - bi) { t -= NTILE - bi; ++bi; }
    int bj = bi + t;
    int b = blockIdx.y;
    int bL = b * LSEQ;
    int i0 = bi * TILE, j0 = bj * TILE;
    bool domirror = (bi != bj);

    if (tid == 0) {
#pragma unroll
        for (int s = 0; s < NSTAGES; ++s) {
            MBARRIER_INIT(fullb + s * 8, 1);
            MBARRIER_INIT(emptyb + s * 8, 8);
        }
    }
    __syncthreads();

#define ISSUE(c)                                                              \
    do {                                                                      \
        int s_ = (c) % NSTAGES;                                               \
        unsigned st_ = sb + (unsigned)s_ * STAGE_B;                           \
        unsigned bar_ = fullb + s_ * 8;                                       \
        int k0_ = (c) * KCHUNK;                                               \
        MBARRIER_EXPECT_TX(bar_, STAGE_B);                                    \
        TMA_LOAD_2D(st_ + 0 * ARR_B, &mhi, k0_, bL + i0, bar_);               \
        TMA_LOAD_2D(st_ + 1 * ARR_B, &mlo, k0_, bL + i0, bar_);               \
        TMA_LOAD_2D(st_ + 2 * ARR_B, &mhi, k0_, bL + j0, bar_);               \
        TMA_LOAD_2D(st_ + 3 * ARR_B, &mlo, k0_, bL + j0, bar_);               \
    } while (0)

    if (tid == 0) {
        ISSUE(0); ISSUE(1); ISSUE(2);
    }

    float acc[4][4][4];
#pragma unroll
    for (int mi = 0; mi < 4; ++mi)
#pragma unroll
        for (int ni = 0; ni < 4; ++ni)
#pragma unroll
            for (int r = 0; r < 4; ++r) acc[mi][ni][r] = 0.f;

    int row_a = warp_m * 64 + (lane & 15);
    unsigned xka = (unsigned)(((row_a >> 1) & 3) << 4);
    int row_b = warp_n * 32 + (lane & 7) + ((lane >> 4) << 3);
    unsigned xkb = (unsigned)(((row_b >> 1) & 3) << 4);
    unsigned ca0 = (unsigned)((lane >> 4) << 4);
    unsigned cb0 = (unsigned)(((lane >> 3) & 1) << 4);

#pragma unroll 1
    for (int c = 0; c < NCHUNK; ++c) {
        int s = c % NSTAGES;
        unsigned ph = (unsigned)((c / NSTAGES) & 1);
        MBARRIER_WAIT_PARITY(fullb + s * 8, ph);

        unsigned st = sb + (unsigned)s * STAGE_B;
        unsigned baseA = st + (unsigned)row_a * ROWB;
        unsigned baseB = st + 2 * ARR_B + (unsigned)row_b * ROWB;

#pragma unroll
        for (int ks = 0; ks < 2; ++ks) {
            unsigned ca = (ca0 | (unsigned)(ks << 5)) ^ xka;
            unsigned cb = (cb0 | (unsigned)(ks << 5)) ^ xkb;
            unsigned aAhi = baseA + ca;
            unsigned aB = baseB + cb;

            unsigned bh[8], bl[8];
            unsigned ah[4][4], al[4][4];
            LDSM4(&bh[0], aB);
            LDSM4(&bh[4], aB + 1024);
            LDSM4(&bl[0], aB + ARR_B);
            LDSM4(&bl[4], aB + ARR_B + 1024);
#pragma unroll
            for (int mi = 0; mi < 4; ++mi) LDSM4(ah[mi], aAhi + mi * 1024);

#pragma unroll
            for (int mi = 0; mi < 4; ++mi)
#pragma unroll
                for (int ni = 0; ni < 4; ++ni) MMA_BF16(acc[mi][ni], ah[mi], &bh[2 * ni]);

#pragma unroll
            for (int mi = 0; mi < 4; ++mi) LDSM4(al[mi], aAhi + ARR_B + mi * 1024);

#pragma unroll
            for (int mi = 0; mi < 4; ++mi)
#pragma unroll
                for (int ni = 0; ni < 4; ++ni) MMA_BF16(acc[mi][ni], ah[mi], &bl[2 * ni]);

#pragma unroll
            for (int mi = 0; mi < 4; ++mi)
#pragma unroll
                for (int ni = 0; ni < 4; ++ni) MMA_BF16(acc[mi][ni], al[mi], &bh[2 * ni]);
        }

        if (lane == 0) MBARRIER_ARRIVE(emptyb + s * 8);
        if (tid == 0 && c + NSTAGES < NCHUNK) {
            MBARRIER_WAIT_PARITY(emptyb + s * 8, ph);
            ISSUE(c + NSTAGES);
        }
    }
    __syncthreads();

    // ---- epilogue ----
    int m_i32 = g_mask_i32;
    float* tb = (float*)smem_base + wid * (32 * 33);
    int jc0 = j0 + warp_n * 32;
    unsigned mj = __ballot_sync(0xFFFFFFFFu, is_masked(mask, bL + jc0 + lane, m_i32));
    const float* kpM = g_kp + (size_t)(bL + jc0 + lane) * CDIST;

#pragma unroll 1
    for (int ch = 0; ch < 2; ++ch) {
        int ib0 = i0 + warp_m * 64 + ch * 32;
        unsigned mib = __ballot_sync(0xFFFFFFFFu, is_masked(mask, bL + ib0 + lane, m_i32));

#pragma unroll
        for (int mi2 = 0; mi2 < 2; ++mi2) {
            int mi = ch * 2 + mi2;
#pragma unroll
            for (int ni = 0; ni < 4; ++ni) {
                int r = mi2 * 16 + lr;
                int cb = ni * 8 + lc * 2;
                tb[r * 33 + cb]           = acc[mi][ni][0];
                tb[r * 33 + cb + 1]       = acc[mi][ni][1];
                tb[(r + 8) * 33 + cb]     = acc[mi][ni][2];
                tb[(r + 8) * 33 + cb + 1] = acc[mi][ni][3];
            }
        }
        __syncwarp();

        int diff = jc0 - ib0;

        {
            int ir = ib0 + lane;
            const float* kpR = g_kp + (size_t)(bL + ir) * CDIST;
            float v[32];
            if (diff >= 41 || diff <= -41) {
                float kc = __ldg(kpR + (diff >= 41 ? 20 : 0));
#pragma unroll
                for (int cc = 0; cc < 32; ++cc) {
                    float x = tb[lane * 33 + cc] + kc;
                    v[cc] = ((mj >> cc) & 1u) ? -1e20f : x;
                }
            } else {
#pragma unroll
                for (int cc = 0; cc < 32; ++cc) {
                    int dd = (jc0 + cc) - ir;
                    dd = min(CLIPD, max(-CLIPD, dd)) + CLIPD;
                    float x = tb[lane * 33 + cc] + __ldg(kpR + dd);
                    v[cc] = ((mj >> cc) & 1u) ? -1e20f : x;
                }
            }
            float* op = out + (size_t)(bL + ir) * LSEQ + jc0;
#pragma unroll
            for (int p = 0; p < 8; ++p)
                ((float4*)op)[p] = make_float4(v[4 * p], v[4 * p + 1], v[4 * p + 2], v[4 * p + 3]);
        }

        if (domirror) {
            int jr = jc0 + lane;
            float v[32];
            if (diff >= 41 || diff <= -41) {
                float kc = __ldg(kpM + (diff >= 41 ? 0 : 20));
#pragma unroll
                for (int cc = 0; cc < 32; ++cc) {
                    float x = tb[cc * 33 + lane] + kc;
                    v[cc] = ((mib >> cc) & 1u) ? -1e20f : x;
                }
            } else {
#pragma unroll
                for (int cc = 0; cc < 32; ++cc) {
                    int dd = (ib0 + cc) - jr;
                    dd = min(CLIPD, max(-CLIPD, dd)) + CLIPD;
                    float x = tb[cc * 33 + lane] + __ldg(kpM + dd);
                    v[cc] = ((mib >> cc) & 1u) ? -1e20f : x;
                }
            }
            float* op = out + (size_t)(bL + jr) * LSEQ + ib0;
#pragma unroll
            for (int p = 0; p < 8; ++p)
                ((float4*)op)[p] = make_float4(v[4 * p], v[4 * p + 1], v[4 * p + 2], v[4 * p + 3]);
        }
        __syncwarp();
    }
}

// ---------------------------------------------------------------------------
// Row softmax (in place) — hardware __expf
// ---------------------------------------------------------------------------
__global__ __launch_bounds__(256) void softmax_rows_kernel(float* __restrict__ out) {
    __shared__ float red[8];
    int t = threadIdx.x;
    float* p = out + (size_t)blockIdx.x * LSEQ + t * 8;
    float4 v0 = *(const float4*)p;
    float4 v1 = *(const float4*)(p + 4);
    float v[8] = {v0.x, v0.y, v0.z, v0.w, v1.x, v1.y, v1.z, v1.w};

    float m = v[0];
#pragma unroll
    for (int i = 1; i < 8; ++i) m = fmaxf(m, v[i]);
#pragma unroll
    for (int o = 16; o > 0; o >>= 1) m = fmaxf(m, __shfl_xor_sync(0xFFFFFFFFu, m, o));
    if ((t & 31) == 0) red[t >> 5] = m;
    __syncthreads();
    float mm = red[0];
#pragma unroll
    for (int i = 1; i < 8; ++i) mm = fmaxf(mm, red[i]);
    __syncthreads();

    float e[8], s = 0.f;
#pragma unroll
    for (int i = 0; i < 8; ++i) { e[i] = __expf(v[i] - mm); s += e[i]; }
#pragma unroll
    for (int o = 16; o > 0; o >>= 1) s += __shfl_xor_sync(0xFFFFFFFFu, s, o);
    if ((t & 31) == 0) red[t >> 5] = s;
    __syncthreads();
    float tot = 0.f;
#pragma unroll
    for (int i = 0; i < 8; ++i) tot += red[i];
    float inv = 1.0f / tot;

    *(float4*)p = make_float4(e[0] * inv, e[1] * inv, e[2] * inv, e[3] * inv);
    *(float4*)(p + 4) = make_float4(e[4] * inv, e[5] * inv, e[6] * inv, e[7] * inv);
}

// ---------------------------------------------------------------------------
typedef CUresult (*PFN_encodeTiled)(CUtensorMap*, CUtensorMapDataType, cuuint32_t, void*,
                                    const cuuint64_t*, const cuuint64_t*, const cuuint32_t*,
                                    const cuuint32_t*, CUtensorMapInterleave, CUtensorMapSwizzle,
                                    CUtensorMapL2promotion, CUtensorMapFloatOOBfill);

extern "C" void kernel_launch(void* const* d_in, const int* in_sizes, int n_in,
                              void* d_out, int out_size) {
    const float* key = (const float*)d_in[0];
    const void* mask = d_in[1];
    const float* params = (const float*)d_in[2];
    float* out = (float*)d_out;

    void* khi_ptr = nullptr;
    void* klo_ptr = nullptr;
    cudaGetSymbolAddress(&khi_ptr, g_khi);
    cudaGetSymbolAddress(&klo_ptr, g_klo);

    void* fn = nullptr;
    cudaDriverEntryPointQueryResult qr;
    cudaGetDriverEntryPointByVersion("cuTensorMapEncodeTiled", &fn, 12000,
                                     cudaEnableDefault, &qr);
    PFN_encodeTiled enc = (PFN_encodeTiled)fn;

    CUtensorMap mhi, mlo;
    cuuint64_t dims[2] = {DIM, (cuuint64_t)BATCH * LSEQ};
    cuuint64_t strides[1] = {DIM * sizeof(__nv_bfloat16)};
    cuuint32_t box[2] = {KCHUNK, 128};
    cuuint32_t estr[2] = {1, 1};
    enc(&mhi, CU_TENSOR_MAP_DATA_TYPE_BFLOAT16, 2, khi_ptr, dims, strides, box, estr,
        CU_TENSOR_MAP_INTERLEAVE_NONE, CU_TENSOR_MAP_SWIZZLE_64B,
        CU_TENSOR_MAP_L2_PROMOTION_L2_128B, CU_TENSOR_MAP_FLOAT_OOB_FILL_NONE);
    enc(&mlo, CU_TENSOR_MAP_DATA_TYPE_BFLOAT16, 2, klo_ptr, dims, strides, box, estr,
        CU_TENSOR_MAP_INTERLEAVE_NONE, CU_TENSOR_MAP_SWIZZLE_64B,
        CU_TENSOR_MAP_L2_PROMOTION_L2_128B, CU_TENSOR_MAP_FLOAT_OOB_FILL_NONE);

    cudaFuncSetAttribute(attn_mma_kernel, cudaFuncAttributeMaxDynamicSharedMemorySize, SMEM_BYTES);

    detect_mask_kernel<<<1, 256>>>((const unsigned char*)mask);
    prep_kernel<<<BATCH * LSEQ / 8, 256>>>(key, params);
    attn_mma_kernel<<<dim3(NPAIRS, BATCH), 256, SMEM_BYTES>>>(mhi, mlo, mask, out);
    softmax_rows_kernel<<<BATCH * LSEQ, 256>>>(out);
}

// round 15
// speedup vs baseline: 3.3549x; 1.0350x over previous
#include <cuda_runtime.h>
#include <cuda.h>
#include <cuda_bf16.h>
#include <math.h>

// ---------------------------------------------------------------------------
// Problem constants
// ---------------------------------------------------------------------------
#define BATCH 16
#define LSEQ  2048
#define DIM   512
#define CDIST 21
#define CLIPD 10

// GEMM tiling (R8/R12 configuration — best measured)
#define TILE 128
#define NTILE (LSEQ / TILE)      // 16
#define NPAIRS (NTILE * (NTILE + 1) / 2)   // 136
#define KCHUNK 32                // bf16 K elems per TMA stage (64 B rows)
#define NCHUNK (DIM / KCHUNK)    // 16
#define NSTAGES 3
#define ROWB 64
#define ARR_B (128 * ROWB)       // 8192 B
#define STAGE_B (4 * ARR_B)      // 32768 B (Ahi, Alo, Bhi, Blo)
#define PIPE_B (NSTAGES * STAGE_B)          // 98304
#define SMEM_BYTES (PIPE_B + 64 + 1024)

// ---------------------------------------------------------------------------
// Device scratch
// ---------------------------------------------------------------------------
__device__ __align__(1024) __nv_bfloat16 g_khi[BATCH * LSEQ * DIM];
__device__ __align__(1024) __nv_bfloat16 g_klo[BATCH * LSEQ * DIM];
__device__ float g_kp[BATCH * LSEQ * CDIST];
__device__ int   g_mask_i32;

// ---------------------------------------------------------------------------
// PTX helpers
// ---------------------------------------------------------------------------
__device__ __forceinline__ unsigned smem_u32(const void* p) {
    unsigned a;
    asm("{ .reg .u64 t; cvta.to.shared.u64 t, %1; cvt.u32.u64 %0, t; }" : "=r"(a) : "l"(p));
    return a;
}

#define MBARRIER_INIT(addr, cnt) \
    asm volatile("mbarrier.init.shared.b64 [%0], %1;" :: "r"((unsigned)(addr)), "r"((unsigned)(cnt)) : "memory")

#define MBARRIER_EXPECT_TX(addr, bytes) \
    asm volatile("mbarrier.arrive.expect_tx.shared.b64 _, [%0], %1;" :: "r"((unsigned)(addr)), "r"((unsigned)(bytes)) : "memory")

#define MBARRIER_ARRIVE(addr) \
    asm volatile("mbarrier.arrive.shared.b64 _, [%0];" :: "r"((unsigned)(addr)) : "memory")

#define MBARRIER_WAIT_PARITY(addr, parity) do {                                    \
    unsigned _m = (unsigned)(addr); unsigned _p = (unsigned)(parity); unsigned _d; \
    asm volatile("{\n\t.reg .pred p;\n\t"                                          \
        "mbarrier.try_wait.parity.acquire.cta.shared::cta.b64 p, [%1], %2;\n\t"    \
        "selp.b32 %0, 1, 0, p;\n\t}"                                               \
        : "=r"(_d) : "r"(_m), "r"(_p) : "memory");                                 \
    if (!_d) {                                                                     \
        asm volatile("{\n\t.reg .pred P1;\n\t"                                     \
        "WL_%=:\n\t"                                                               \
        "mbarrier.try_wait.parity.acquire.cta.shared::cta.b64 P1, [%0], %1, 0x989680;\n\t" \
        "@P1 bra.uni WD_%=;\n\t"                                                   \
        "bra.uni WL_%=;\n\t"                                                       \
        "WD_%=:\n\t}" :: "r"(_m), "r"(_p) : "memory");                             \
    }                                                                              \
} while (0)

#define TMA_LOAD_2D(dst, map, x, y, mbar) \
    asm volatile("cp.async.bulk.tensor.2d.shared::cta.global.tile.mbarrier::complete_tx::bytes " \
        "[%0], [%1, {%2, %3}], [%4];" \
        :: "r"((unsigned)(dst)), "l"(map), "r"((int)(x)), "r"((int)(y)), "r"((unsigned)(mbar)) : "memory")

#define LDSM4(r, addr)                                                        \
    asm volatile("ldmatrix.sync.aligned.m8n8.x4.shared.b16 {%0,%1,%2,%3}, [%4];" \
        : "=r"((r)[0]), "=r"((r)[1]), "=r"((r)[2]), "=r"((r)[3]) : "r"(addr))

#define MMA_BF16(d, a, b)                                                     \
    asm volatile(                                                             \
        "mma.sync.aligned.m16n8k16.row.col.f32.bf16.bf16.f32 "                \
        "{%0,%1,%2,%3}, {%4,%5,%6,%7}, {%8,%9}, {%0,%1,%2,%3};"               \
        : "+f"((d)[0]), "+f"((d)[1]), "+f"((d)[2]), "+f"((d)[3])              \
        : "r"((a)[0]), "r"((a)[1]), "r"((a)[2]), "r"((a)[3]),                 \
          "r"((b)[0]), "r"((b)[1]))

// ---------------------------------------------------------------------------
// Mask dtype detection (bool vs int32) — parallel, one block
// ---------------------------------------------------------------------------
__global__ __launch_bounds__(256) void detect_mask_kernel(const unsigned char* m) {
    int tid = threadIdx.x;
    int hit = (m[tid * 4 + 1] | m[tid * 4 + 2] | m[tid * 4 + 3]) != 0;
    int any = __syncthreads_or(hit);
    if (tid == 0) g_mask_i32 = (any == 0);
}

__device__ __forceinline__ bool is_masked(const void* mask, int idx, int m_i32) {
    if (m_i32) return ((const int*)mask)[idx] != 0;
    return ((const unsigned char*)mask)[idx] != 0;
}

__device__ __forceinline__ unsigned pack_bf16x2(float a, float b) {
    __nv_bfloat162 t = __floats2bfloat162_rn(a, b);
    return *reinterpret_cast<unsigned*>(&t);
}

// ---------------------------------------------------------------------------
// FUSED prep (4 rows per warp): one pass over key.
//   - split fp32 -> (hi, lo) bf16 (float4 loads, uint2 bf16x4 stores)
//   - kp[b,i,c] = key[b,i,:] . params[c,:] — params SMEM pass amortized
//     across 4 rows (4x less shared-memory traffic).
// ---------------------------------------------------------------------------
__global__ __launch_bounds__(256) void prep_kernel(const float* __restrict__ key,
                                                   const float* __restrict__ params) {
    __shared__ float sp[CDIST * DIM];
    int tid = threadIdx.x;
    for (int i = tid; i < CDIST * DIM / 4; i += 256)
        ((float4*)sp)[i] = ((const float4*)params)[i];
    __syncthreads();

    int warp = tid >> 5, lane = tid & 31;
    int row0 = blockIdx.x * 32 + warp * 4;   // 4 consecutive rows per warp

    // load 4 rows: kr[r][t], r=row, t=float4 chunk
    float4 kr[4][4];
#pragma unroll
    for (int r = 0; r < 4; ++r) {
        const float4* krow4 = (const float4*)(key + (size_t)(row0 + r) * DIM);
#pragma unroll
        for (int t = 0; t < 4; ++t) kr[r][t] = krow4[lane + 32 * t];
    }

    // split -> bf16 hi/lo, packed 8B stores, 4 rows
#pragma unroll
    for (int r = 0; r < 4; ++r) {
        uint2* hrow = (uint2*)(g_khi + (size_t)(row0 + r) * DIM);
        uint2* lrow = (uint2*)(g_klo + (size_t)(row0 + r) * DIM);
#pragma unroll
        for (int t = 0; t < 4; ++t) {
            float4 v = kr[r][t];
            float hx = __bfloat162float(__float2bfloat16_rn(v.x));
            float hy = __bfloat162float(__float2bfloat16_rn(v.y));
            float hz = __bfloat162float(__float2bfloat16_rn(v.z));
            float hw = __bfloat162float(__float2bfloat16_rn(v.w));
            uint2 hp, lp;
            hp.x = pack_bf16x2(hx, hy);
            hp.y = pack_bf16x2(hz, hw);
            lp.x = pack_bf16x2(v.x - hx, v.y - hy);
            lp.y = pack_bf16x2(v.z - hz, v.w - hw);
            hrow[lane + 32 * t] = hp;
            lrow[lane + 32 * t] = lp;
        }
    }

    // kp: one sp pass per c serves all 4 rows
    const float4* sp4 = (const float4*)sp;
#pragma unroll 1
    for (int c = 0; c < CDIST; ++c) {
        float4 p[4];
#pragma unroll
        for (int t = 0; t < 4; ++t) p[t] = sp4[c * (DIM / 4) + lane + 32 * t];
        float a[4];
#pragma unroll
        for (int r = 0; r < 4; ++r) {
            float s = 0.f;
#pragma unroll
            for (int t = 0; t < 4; ++t)
                s += kr[r][t].x * p[t].x + kr[r][t].y * p[t].y +
                     kr[r][t].z * p[t].z + kr[r][t].w * p[t].w;
            a[r] = s;
        }
#pragma unroll
        for (int o = 16; o > 0; o >>= 1)
#pragma unroll
            for (int r = 0; r < 4; ++r)
                a[r] += __shfl_xor_sync(0xFFFFFFFFu, a[r], o);
        if (lane == 0) {
#pragma unroll
            for (int r = 0; r < 4; ++r)
                g_kp[(size_t)(row0 + r) * CDIST + c] = a[r];
        }
    }
}

// ---------------------------------------------------------------------------
// Main GEMM (R8 config): 3x-bf16 mma.sync + ldmatrix, TMA-fed 3-stage
// pipeline, 8 warps of 64x32, 3 passes of 16 independent MMAs,
// triangular symmetric tiles, banded bias + mask epilogue.
// ---------------------------------------------------------------------------
__global__ __launch_bounds__(256, 2) void attn_mma_kernel(
    const __grid_constant__ CUtensorMap mhi,
    const __grid_constant__ CUtensorMap mlo,
    const void* __restrict__ mask,
    float* __restrict__ out) {
    extern __shared__ char smem_raw[];
    unsigned sb_raw = smem_u32(smem_raw);
    unsigned sb = (sb_raw + 1023u) & ~1023u;
    char* smem_base = smem_raw + (sb - sb_raw);
    unsigned fullb = sb + PIPE_B;
    unsigned emptyb = fullb + NSTAGES * 8;

    int tid = threadIdx.x;
    int wid = tid >> 5;
    int lane = tid & 31;
    int lr = lane >> 2;
    int lc = lane & 3;
    int warp_m = wid & 1;
    int warp_n = wid >> 1;

    int t = blockIdx.x;
    int bi = 0;
    while (t >= NTILE - bi) { t -= NTILE - bi; ++bi; }
    int bj = bi + t;
    int b = blockIdx.y;
    int bL = b * LSEQ;
    int i0 = bi * TILE, j0 = bj * TILE;
    bool domirror = (bi != bj);

    if (tid == 0) {
#pragma unroll
        for (int s = 0; s < NSTAGES; ++s) {
            MBARRIER_INIT(fullb + s * 8, 1);
            MBARRIER_INIT(emptyb + s * 8, 8);
        }
    }
    __syncthreads();

#define ISSUE(c)                                                              \
    do {                                                                      \
        int s_ = (c) % NSTAGES;                                               \
        unsigned st_ = sb + (unsigned)s_ * STAGE_B;                           \
        unsigned bar_ = fullb + s_ * 8;                                       \
        int k0_ = (c) * KCHUNK;                                               \
        MBARRIER_EXPECT_TX(bar_, STAGE_B);                                    \
        TMA_LOAD_2D(st_ + 0 * ARR_B, &mhi, k0_, bL + i0, bar_);               \
        TMA_LOAD_2D(st_ + 1 * ARR_B, &mlo, k0_, bL + i0, bar_);               \
        TMA_LOAD_2D(st_ + 2 * ARR_B, &mhi, k0_, bL + j0, bar_);               \
        TMA_LOAD_2D(st_ + 3 * ARR_B, &mlo, k0_, bL + j0, bar_);               \
    } while (0)

    if (tid == 0) {
        ISSUE(0); ISSUE(1); ISSUE(2);
    }

    float acc[4][4][4];
#pragma unroll
    for (int mi = 0; mi < 4; ++mi)
#pragma unroll
        for (int ni = 0; ni < 4; ++ni)
#pragma unroll
            for (int r = 0; r < 4; ++r) acc[mi][ni][r] = 0.f;

    int row_a = warp_m * 64 + (lane & 15);
    unsigned xka = (unsigned)(((row_a >> 1) & 3) << 4);
    int row_b = warp_n * 32 + (lane & 7) + ((lane >> 4) << 3);
    unsigned xkb = (unsigned)(((row_b >> 1) & 3) << 4);
    unsigned ca0 = (unsigned)((lane >> 4) << 4);
    unsigned cb0 = (unsigned)(((lane >> 3) & 1) << 4);

#pragma unroll 1
    for (int c = 0; c < NCHUNK; ++c) {
        int s = c % NSTAGES;
        unsigned ph = (unsigned)((c / NSTAGES) & 1);
        MBARRIER_WAIT_PARITY(fullb + s * 8, ph);

        unsigned st = sb + (unsigned)s * STAGE_B;
        unsigned baseA = st + (unsigned)row_a * ROWB;
        unsigned baseB = st + 2 * ARR_B + (unsigned)row_b * ROWB;

#pragma unroll
        for (int ks = 0; ks < 2; ++ks) {
            unsigned ca = (ca0 | (unsigned)(ks << 5)) ^ xka;
            unsigned cb = (cb0 | (unsigned)(ks << 5)) ^ xkb;
            unsigned aAhi = baseA + ca;
            unsigned aB = baseB + cb;

            unsigned bh[8], bl[8];
            unsigned ah[4][4], al[4][4];
            LDSM4(&bh[0], aB);
            LDSM4(&bh[4], aB + 1024);
            LDSM4(&bl[0], aB + ARR_B);
            LDSM4(&bl[4], aB + ARR_B + 1024);
#pragma unroll
            for (int mi = 0; mi < 4; ++mi) LDSM4(ah[mi], aAhi + mi * 1024);

#pragma unroll
            for (int mi = 0; mi < 4; ++mi)
#pragma unroll
                for (int ni = 0; ni < 4; ++ni) MMA_BF16(acc[mi][ni], ah[mi], &bh[2 * ni]);

#pragma unroll
            for (int mi = 0; mi < 4; ++mi) LDSM4(al[mi], aAhi + ARR_B + mi * 1024);

#pragma unroll
            for (int mi = 0; mi < 4; ++mi)
#pragma unroll
                for (int ni = 0; ni < 4; ++ni) MMA_BF16(acc[mi][ni], ah[mi], &bl[2 * ni]);

#pragma unroll
            for (int mi = 0; mi < 4; ++mi)
#pragma unroll
                for (int ni = 0; ni < 4; ++ni) MMA_BF16(acc[mi][ni], al[mi], &bh[2 * ni]);
        }

        if (lane == 0) MBARRIER_ARRIVE(emptyb + s * 8);
        if (tid == 0 && c + NSTAGES < NCHUNK) {
            MBARRIER_WAIT_PARITY(emptyb + s * 8, ph);
            ISSUE(c + NSTAGES);
        }
    }
    __syncthreads();

    // ---- epilogue ----
    int m_i32 = g_mask_i32;
    float* tb = (float*)smem_base + wid * (32 * 33);
    int jc0 = j0 + warp_n * 32;
    unsigned mj = __ballot_sync(0xFFFFFFFFu, is_masked(mask, bL + jc0 + lane, m_i32));
    const float* kpM = g_kp + (size_t)(bL + jc0 + lane) * CDIST;

#pragma unroll 1
    for (int ch = 0; ch < 2; ++ch) {
        int ib0 = i0 + warp_m * 64 + ch * 32;
        unsigned mib = __ballot_sync(0xFFFFFFFFu, is_masked(mask, bL + ib0 + lane, m_i32));

#pragma unroll
        for (int mi2 = 0; mi2 < 2; ++mi2) {
            int mi = ch * 2 + mi2;
#pragma unroll
            for (int ni = 0; ni < 4; ++ni) {
                int r = mi2 * 16 + lr;
                int cb = ni * 8 + lc * 2;
                tb[r * 33 + cb]           = acc[mi][ni][0];
                tb[r * 33 + cb + 1]       = acc[mi][ni][1];
                tb[(r + 8) * 33 + cb]     = acc[mi][ni][2];
                tb[(r + 8) * 33 + cb + 1] = acc[mi][ni][3];
            }
        }
        __syncwarp();

        int diff = jc0 - ib0;

        {
            int ir = ib0 + lane;
            const float* kpR = g_kp + (size_t)(bL + ir) * CDIST;
            float v[32];
            if (diff >= 41 || diff <= -41) {
                float kc = __ldg(kpR + (diff >= 41 ? 20 : 0));
#pragma unroll
                for (int cc = 0; cc < 32; ++cc) {
                    float x = tb[lane * 33 + cc] + kc;
                    v[cc] = ((mj >> cc) & 1u) ? -1e20f : x;
                }
            } else {
#pragma unroll
                for (int cc = 0; cc < 32; ++cc) {
                    int dd = (jc0 + cc) - ir;
                    dd = min(CLIPD, max(-CLIPD, dd)) + CLIPD;
                    float x = tb[lane * 33 + cc] + __ldg(kpR + dd);
                    v[cc] = ((mj >> cc) & 1u) ? -1e20f : x;
                }
            }
            float* op = out + (size_t)(bL + ir) * LSEQ + jc0;
#pragma unroll
            for (int p = 0; p < 8; ++p)
                ((float4*)op)[p] = make_float4(v[4 * p], v[4 * p + 1], v[4 * p + 2], v[4 * p + 3]);
        }

        if (domirror) {
            int jr = jc0 + lane;
            float v[32];
            if (diff >= 41 || diff <= -41) {
                float kc = __ldg(kpM + (diff >= 41 ? 0 : 20));
#pragma unroll
                for (int cc = 0; cc < 32; ++cc) {
                    float x = tb[cc * 33 + lane] + kc;
                    v[cc] = ((mib >> cc) & 1u) ? -1e20f : x;
                }
            } else {
#pragma unroll
                for (int cc = 0; cc < 32; ++cc) {
                    int dd = (ib0 + cc) - jr;
                    dd = min(CLIPD, max(-CLIPD, dd)) + CLIPD;
                    float x = tb[cc * 33 + lane] + __ldg(kpM + dd);
                    v[cc] = ((mib >> cc) & 1u) ? -1e20f : x;
                }
            }
            float* op = out + (size_t)(bL + jr) * LSEQ + ib0;
#pragma unroll
            for (int p = 0; p < 8; ++p)
                ((float4*)op)[p] = make_float4(v[4 * p], v[4 * p + 1], v[4 * p + 2], v[4 * p + 3]);
        }
        __syncwarp();
    }
}

// ---------------------------------------------------------------------------
// Row softmax (in place) — hardware __expf
// ---------------------------------------------------------------------------
__global__ __launch_bounds__(256) void softmax_rows_kernel(float* __restrict__ out) {
    __shared__ float red[8];
    int t = threadIdx.x;
    float* p = out + (size_t)blockIdx.x * LSEQ + t * 8;
    float4 v0 = *(const float4*)p;
    float4 v1 = *(const float4*)(p + 4);
    float v[8] = {v0.x, v0.y, v0.z, v0.w, v1.x, v1.y, v1.z, v1.w};

    float m = v[0];
#pragma unroll
    for (int i = 1; i < 8; ++i) m = fmaxf(m, v[i]);
#pragma unroll
    for (int o = 16; o > 0; o >>= 1) m = fmaxf(m, __shfl_xor_sync(0xFFFFFFFFu, m, o));
    if ((t & 31) == 0) red[t >> 5] = m;
    __syncthreads();
    float mm = red[0];
#pragma unroll
    for (int i = 1; i < 8; ++i) mm = fmaxf(mm, red[i]);
    __syncthreads();

    float e[8], s = 0.f;
#pragma unroll
    for (int i = 0; i < 8; ++i) { e[i] = __expf(v[i] - mm); s += e[i]; }
#pragma unroll
    for (int o = 16; o > 0; o >>= 1) s += __shfl_xor_sync(0xFFFFFFFFu, s, o);
    if ((t & 31) == 0) red[t >> 5] = s;
    __syncthreads();
    float tot = 0.f;
#pragma unroll
    for (int i = 0; i < 8; ++i) tot += red[i];
    float inv = 1.0f / tot;

    *(float4*)p = make_float4(e[0] * inv, e[1] * inv, e[2] * inv, e[3] * inv);
    *(float4*)(p + 4) = make_float4(e[4] * inv, e[5] * inv, e[6] * inv, e[7] * inv);
}

// ---------------------------------------------------------------------------
typedef CUresult (*PFN_encodeTiled)(CUtensorMap*, CUtensorMapDataType, cuuint32_t, void*,
                                    const cuuint64_t*, const cuuint64_t*, const cuuint32_t*,
                                    const cuuint32_t*, CUtensorMapInterleave, CUtensorMapSwizzle,
                                    CUtensorMapL2promotion, CUtensorMapFloatOOBfill);

extern "C" void kernel_launch(void* const* d_in, const int* in_sizes, int n_in,
                              void* d_out, int out_size) {
    const float* key = (const float*)d_in[0];
    const void* mask = d_in[1];
    const float* params = (const float*)d_in[2];
    float* out = (float*)d_out;

    void* khi_ptr = nullptr;
    void* klo_ptr = nullptr;
    cudaGetSymbolAddress(&khi_ptr, g_khi);
    cudaGetSymbolAddress(&klo_ptr, g_klo);

    void* fn = nullptr;
    cudaDriverEntryPointQueryResult qr;
    cudaGetDriverEntryPointByVersion("cuTensorMapEncodeTiled", &fn, 12000,
                                     cudaEnableDefault, &qr);
    PFN_encodeTiled enc = (PFN_encodeTiled)fn;

    CUtensorMap mhi, mlo;
    cuuint64_t dims[2] = {DIM, (cuuint64_t)BATCH * LSEQ};
    cuuint64_t strides[1] = {DIM * sizeof(__nv_bfloat16)};
    cuuint32_t box[2] = {KCHUNK, 128};
    cuuint32_t estr[2] = {1, 1};
    enc(&mhi, CU_TENSOR_MAP_DATA_TYPE_BFLOAT16, 2, khi_ptr, dims, strides, box, estr,
        CU_TENSOR_MAP_INTERLEAVE_NONE, CU_TENSOR_MAP_SWIZZLE_64B,
        CU_TENSOR_MAP_L2_PROMOTION_L2_128B, CU_TENSOR_MAP_FLOAT_OOB_FILL_NONE);
    enc(&mlo, CU_TENSOR_MAP_DATA_TYPE_BFLOAT16, 2, klo_ptr, dims, strides, box, estr,
        CU_TENSOR_MAP_INTERLEAVE_NONE, CU_TENSOR_MAP_SWIZZLE_64B,
        CU_TENSOR_MAP_L2_PROMOTION_L2_128B, CU_TENSOR_MAP_FLOAT_OOB_FILL_NONE);

    cudaFuncSetAttribute(attn_mma_kernel, cudaFuncAttributeMaxDynamicSharedMemorySize, SMEM_BYTES);

    detect_mask_kernel<<<1, 256>>>((const unsigned char*)mask);
    prep_kernel<<<BATCH * LSEQ / 32, 256>>>(key, params);
    attn_mma_kernel<<<dim3(NPAIRS, BATCH), 256, SMEM_BYTES>>>(mhi, mlo, mask, out);
    softmax_rows_kernel<<<BATCH * LSEQ, 256>>>(out);
}